// round 6
// baseline (speedup 1.0000x reference)
#include <cuda_runtime.h>
#include <math.h>

#define NBATCH 64
#define NSTEP  128
#define MEMD   128
#define NSLOT  20
#define HSLOT  10
#define NCTA   128
#define OUTC   160
#define RSTR   12      // floats per mem_s row (48B, 16B aligned)

__device__ float g_S [NBATCH * NSTEP * MEMD];
__device__ float g_O [NBATCH * NSTEP * OUTC];
__device__ float g_WK[OUTC * MEMD];
__device__ float g_BK[OUTC];
__device__ float g_VK[NSLOT * MEMD];
__device__ uint2 g_part[NSTEP][NSLOT][NBATCH];   // {value bits, tag = t+1}
__device__ float g_H [NBATCH * NSLOT * MEMD];

// ---------- helpers ----------
__device__ __forceinline__ void ffma2(unsigned long long &acc, unsigned long long a,
                                      unsigned long long b) {
    asm("fma.rn.f32x2 %0, %1, %2, %0;" : "+l"(acc) : "l"(a), "l"(b));
}
__device__ __forceinline__ unsigned long long add2(unsigned long long a,
                                                   unsigned long long b) {
    unsigned long long r;
    asm("add.rn.f32x2 %0, %1, %2;" : "=l"(r) : "l"(a), "l"(b));
    return r;
}
__device__ __forceinline__ unsigned long long pack2(float x) {
    unsigned long long r; asm("mov.b64 %0, {%1, %1};" : "=l"(r) : "f"(x)); return r;
}
__device__ __forceinline__ float2 up2(unsigned long long v) {
    float2 r; asm("mov.b64 {%0, %1}, %2;" : "=f"(r.x), "=f"(r.y) : "l"(v)); return r;
}
__device__ __forceinline__ unsigned smem_u32(const void* p) {
    return (unsigned)__cvta_generic_to_shared(p);
}
// 16B shared load -> two packed f32x2
__device__ __forceinline__ void ldsA(unsigned addr, unsigned long long &m0,
                                     unsigned long long &m1) {
    asm("{\n\t"
        ".reg .b32 t0,t1,t2,t3;\n\t"
        "ld.shared.v4.b32 {t0,t1,t2,t3}, [%2];\n\t"
        "mov.b64 %0, {t0,t1};\n\t"
        "mov.b64 %1, {t2,t3};\n\t"
        "}" : "=l"(m0), "=l"(m1) : "r"(addr));
}
__device__ __forceinline__ unsigned long long ldsB(unsigned addr) {
    unsigned long long r;
    asm("{\n\t"
        ".reg .b32 t0,t1;\n\t"
        "ld.shared.v2.b32 {t0,t1}, [%1];\n\t"
        "mov.b64 %0, {t0,t1};\n\t"
        "}" : "=l"(r) : "r"(addr));
    return r;
}
__device__ __forceinline__ uint2 ldv2(const uint2* p) {
    uint2 v;
    asm volatile("ld.volatile.global.v2.u32 {%0,%1}, [%2];"
                 : "=r"(v.x), "=r"(v.y) : "l"(p) : "memory");
    return v;
}
__device__ __forceinline__ void stv2(uint2* p, uint2 v) {
    asm volatile("st.volatile.global.v2.u32 [%0], {%1,%2};"
                 :: "l"(p), "r"(v.x), "r"(v.y) : "memory");
}
__device__ __forceinline__ float sig(float x) { return 1.f / (1.f + __expf(-x)); }

// ---------- prologue: weights pack + Vkey + zero tag buffer ----------
__global__ void k_setup(const float* __restrict__ Ww, const float* __restrict__ Wb,
                        const float* __restrict__ sk, const float* __restrict__ Vw,
                        const float* __restrict__ Vb) {
    int bid = blockIdx.x, tid = threadIdx.x;
    if (bid < NSLOT) {
        float acc = Vb[tid];
        const float* skr = sk + bid * MEMD;
        const float* vwr = Vw + tid * MEMD;
        #pragma unroll 8
        for (int m = 0; m < MEMD; m++) acc += skr[m] * vwr[m];
        g_VK[bid * MEMD + tid] = acc;
    } else if (bid == NSLOT) {
        for (int idx = tid; idx < OUTC * MEMD; idx += 128) {
            int c = idx >> 7, m = idx & 127;
            float v = 0.f;
            if (c < 128)      v = Ww[c * MEMD + m];
            else if (c < 148) v = sk[(c - 128) * MEMD + m];
            g_WK[idx] = v;
        }
        for (int idx = tid; idx < OUTC; idx += 128)
            g_BK[idx] = (idx < 128) ? Wb[idx] : 0.f;
    } else {
        int base = (bid - 21) * 128 + tid;
        ((uint4*)g_part)[base]         = make_uint4(0u, 0u, 0u, 0u);
        ((uint4*)g_part)[base + 40960] = make_uint4(0u, 0u, 0u, 0u);
    }
}

__global__ void k_gather(const int* __restrict__ ids, const float* __restrict__ E) {
    int idx = blockIdx.x * 256 + threadIdx.x;
    int row = idx >> 5, q = idx & 31;
    int b = row >> 7, t = row & 127;
    int tok = __ldg(&ids[b * 4096 + t]);
    ((float4*)g_S)[row * 32 + q] = ((const float4*)E)[tok * 32 + q];
}

__global__ void __launch_bounds__(256) k_gemm() {
    __shared__ float Ss[64][33];
    __shared__ float Ks[OUTC][33];
    int tid = threadIdx.x, row0 = blockIdx.x * 64;
    int tx = tid & 15, ty = tid >> 4;
    float acc[4][10];
    #pragma unroll
    for (int i = 0; i < 4; i++)
        #pragma unroll
        for (int j = 0; j < 10; j++) acc[i][j] = 0.f;
    for (int kk = 0; kk < 128; kk += 32) {
        #pragma unroll
        for (int i = 0; i < 8; i++) {
            int idx = tid + i * 256, r = idx >> 5, k = idx & 31;
            Ss[r][k] = g_S[(row0 + r) * 128 + kk + k];
        }
        #pragma unroll
        for (int i = 0; i < 20; i++) {
            int idx = tid + i * 256, c = idx >> 5, k = idx & 31;
            Ks[c][k] = g_WK[c * 128 + kk + k];
        }
        __syncthreads();
        #pragma unroll
        for (int k = 0; k < 32; k++) {
            float a[4], bv[10];
            #pragma unroll
            for (int i = 0; i < 4; i++)  a[i]  = Ss[ty * 4 + i][k];
            #pragma unroll
            for (int j = 0; j < 10; j++) bv[j] = Ks[tx * 10 + j][k];
            #pragma unroll
            for (int i = 0; i < 4; i++)
                #pragma unroll
                for (int j = 0; j < 10; j++) acc[i][j] = fmaf(a[i], bv[j], acc[i][j]);
        }
        __syncthreads();
    }
    #pragma unroll
    for (int i = 0; i < 4; i++)
        #pragma unroll
        for (int j = 0; j < 10; j++) {
            int r = row0 + ty * 4 + i, c = tx * 10 + j;
            g_O[r * OUTC + c] = acc[i][j] + g_BK[c];
        }
}

// ---------- persistent scan: NT=4 register reuse, 8-way m-split, j-split ----------
__global__ void __launch_bounds__(512, 1) k_main(const float* __restrict__ Uw,
                                                 const float* __restrict__ Ub) {
    __shared__ __align__(16) float mem_s[128 * RSTR];   // RAW (unnormalized) mem
    __shared__ __align__(16) unsigned long long hbuf[128 * 6];  // h pairs per n
    __shared__ float vk_s[HSLOT][128];
    __shared__ float s_b[2][128], ws_b[2][128];
    __shared__ float sk_b[2][12];
    __shared__ float red_s[8][5];                // gate partials
    __shared__ float red2_s[16][4];              // sumsq partials per warp
    __shared__ float inv_s[HSLOT];

    const int tid = threadIdx.x;
    const int n = tid & 127, q = tid >> 7, wid = tid >> 5, lane = tid & 31;
    const int cta = blockIdx.x, b = cta >> 1, half = cta & 1;

    // matmul role: jB = pairs {2,3,4} for warps 8-15, jA = pairs {0,1} for warps 0-7
    const int jB = (wid >= 8);
    const int ntile = ((wid & 7) << 2) | (lane >> 3);   // 0..31
    const int n0 = ntile << 2;                          // output cols n0..n0+3
    const int msplit = lane & 7;                        // m = k*8 + msplit

    // Uw slice: uw[nt][k] = Uw[n0+nt][k*8+msplit]  (64 registers)
    float uw[4][16];
    #pragma unroll
    for (int nt = 0; nt < 4; nt++)
        #pragma unroll
        for (int k = 0; k < 16; k++)
            uw[nt][k] = Uw[(n0 + nt) * 128 + k * 8 + msplit];

    const float ubn = Ub[n];
    for (int idx = tid; idx < HSLOT * 128; idx += 512)
        vk_s[idx >> 7][idx & 127] = g_VK[(half * HSLOT + (idx >> 7)) * 128 + (idx & 127)];
    for (int idx = tid; idx < 128 * RSTR; idx += 512) mem_s[idx] = 0.f;

    float memv[4];
    #pragma unroll
    for (int i = 0; i < 4; i++) memv[i] = 0.f;

    const float* Sb = g_S + b * 128 * 128;
    const float* Ob = g_O + b * 128 * OUTC;
    if (tid < 128) { s_b[0][n] = Sb[n]; ws_b[0][n] = Ob[n]; }
    else if (tid < 138) sk_b[0][tid - 128] = Ob[128 + half * HSLOT + (tid - 128)];
    if (tid < HSLOT) inv_s[tid] = 1.f;           // t=0: mem is exactly zero
    __syncthreads();

    const unsigned mbase = smem_u32(mem_s) + msplit * 48 + (jB ? 16 : 0);

    for (int t = 0; t < NSTEP; t++) {
        const int cur = t & 1, nxt = cur ^ 1;

        // ---- staging prefetch (registers) ----
        float s_nxt = 0.f, ws_nxt = 0.f, skey_nxt = 0.f;
        {
            int tn = (t + 1) & 127;
            if (tid < 128) { s_nxt = Sb[tn * 128 + n]; ws_nxt = Ob[tn * OUTC + n]; }
            else if (tid < 138) skey_nxt = Ob[tn * OUTC + 128 + half * HSLOT + (tid - 128)];
        }

        // ---- gate dots (warps 0-7; slots split 0-4 / 5-9) ----
        if (tid < 256) {
            float sv = s_b[cur][n];
            const float* row = mem_s + n * RSTR + (tid >> 7) * 5;
            float p0 = sv * row[0], p1 = sv * row[1], p2 = sv * row[2];
            float p3 = sv * row[3], p4 = sv * row[4];
            #pragma unroll
            for (int s = 16; s; s >>= 1) {
                p0 += __shfl_xor_sync(~0u, p0, s);
                p1 += __shfl_xor_sync(~0u, p1, s);
                p2 += __shfl_xor_sync(~0u, p2, s);
                p3 += __shfl_xor_sync(~0u, p3, s);
                p4 += __shfl_xor_sync(~0u, p4, s);
            }
            if (lane == 0) {
                float* rr = red_s[wid];
                rr[0] = p0; rr[1] = p1; rr[2] = p2; rr[3] = p3; rr[4] = p4;
            }
        }

        // ---- matmul: NT=4 columns per thread, 16 m-rows ----
        if (!jB) {
            unsigned long long a0[4], a1[4];
            #pragma unroll
            for (int i = 0; i < 4; i++) { a0[i] = 0ull; a1[i] = 0ull; }
            #pragma unroll
            for (int k = 0; k < 16; k++) {
                unsigned long long m0, m1;
                ldsA(mbase + k * 384, m0, m1);
                #pragma unroll
                for (int nt = 0; nt < 4; nt++) {
                    unsigned long long u2 = pack2(uw[nt][k]);
                    ffma2(a0[nt], u2, m0);
                    ffma2(a1[nt], u2, m1);
                }
            }
            #pragma unroll
            for (int d = 1; d < 8; d <<= 1)
                #pragma unroll
                for (int nt = 0; nt < 4; nt++) {
                    a0[nt] = add2(a0[nt], __shfl_xor_sync(~0u, a0[nt], d));
                    a1[nt] = add2(a1[nt], __shfl_xor_sync(~0u, a1[nt], d));
                }
            if (msplit == 0) {
                #pragma unroll
                for (int nt = 0; nt < 4; nt++) {
                    ulonglong2 v; v.x = a0[nt]; v.y = a1[nt];
                    *(ulonglong2*)&hbuf[(n0 + nt) * 6] = v;
                }
            }
        } else {
            unsigned long long a0[4], a1[4], a2[4];
            #pragma unroll
            for (int i = 0; i < 4; i++) { a0[i] = 0ull; a1[i] = 0ull; a2[i] = 0ull; }
            #pragma unroll
            for (int k = 0; k < 16; k++) {
                unsigned long long m0, m1, m2;
                ldsA(mbase + k * 384, m0, m1);
                m2 = ldsB(mbase + k * 384 + 16);
                #pragma unroll
                for (int nt = 0; nt < 4; nt++) {
                    unsigned long long u2 = pack2(uw[nt][k]);
                    ffma2(a0[nt], u2, m0);
                    ffma2(a1[nt], u2, m1);
                    ffma2(a2[nt], u2, m2);
                }
            }
            #pragma unroll
            for (int d = 1; d < 8; d <<= 1)
                #pragma unroll
                for (int nt = 0; nt < 4; nt++) {
                    a0[nt] = add2(a0[nt], __shfl_xor_sync(~0u, a0[nt], d));
                    a1[nt] = add2(a1[nt], __shfl_xor_sync(~0u, a1[nt], d));
                    a2[nt] = add2(a2[nt], __shfl_xor_sync(~0u, a2[nt], d));
                }
            if (msplit == 0) {
                #pragma unroll
                for (int nt = 0; nt < 4; nt++) {
                    ulonglong2 v; v.x = a0[nt]; v.y = a1[nt];
                    *(ulonglong2*)&hbuf[(n0 + nt) * 6 + 2] = v;
                    hbuf[(n0 + nt) * 6 + 4] = a2[nt];
                }
            }
        }

        // ---- poll norms (warps 0-4) ----
        if (t && wid < 5) {
            int j = tid >> 4, i = tid & 15;
            const uint2* pp = &g_part[t - 1][half * HSLOT + j][i];
            const unsigned want = (unsigned)t;
            uint2 v0 = ldv2(pp), v1 = ldv2(pp + 16), v2 = ldv2(pp + 32), v3 = ldv2(pp + 48);
            while ((v0.y ^ want) | (v1.y ^ want) | (v2.y ^ want) | (v3.y ^ want)) {
                v0 = ldv2(pp); v1 = ldv2(pp + 16); v2 = ldv2(pp + 32); v3 = ldv2(pp + 48);
            }
            float acc = __uint_as_float(v0.x) + __uint_as_float(v1.x)
                      + __uint_as_float(v2.x) + __uint_as_float(v3.x);
            acc += __shfl_xor_sync(~0u, acc, 8);
            acc += __shfl_xor_sync(~0u, acc, 4);
            acc += __shfl_xor_sync(~0u, acc, 2);
            acc += __shfl_xor_sync(~0u, acc, 1);
            if (i == 0) inv_s[j] = rsqrtf(acc);
        }
        __syncthreads();   // hbuf + red_s + inv_s visible

        // ---- epilogue: gate, relu, update, sumsq (q-split over slot pairs) ----
        const float wsv = ws_b[cur][n];
        float* row = mem_s + n * RSTR;
        if (q == 0) {
            ulonglong2 h2 = *(const ulonglong2*)&hbuf[n * 6];
            float sq[4];
            #pragma unroll
            for (int p = 0; p < 2; p++) {
                float2 a = up2(p ? h2.y : h2.x);
                const int j0 = 2 * p, j1 = 2 * p + 1;
                float r0 = red_s[0][j0] + red_s[1][j0] + red_s[2][j0] + red_s[3][j0];
                float r1 = red_s[0][j1] + red_s[1][j1] + red_s[2][j1] + red_s[3][j1];
                float i0 = inv_s[j0], i1 = inv_s[j1];
                float g0 = sig(fmaf(i0, r0, sk_b[cur][j0]));
                float g1 = sig(fmaf(i1, r1, sk_b[cur][j1]));
                float h0 = fmaxf(fmaf(i0, a.x, ubn + vk_s[j0][n] + wsv), 0.f);
                float h1 = fmaxf(fmaf(i1, a.y, ubn + vk_s[j1][n] + wsv), 0.f);
                memv[j0] = fmaf(memv[j0], i0, g0 * h0);
                memv[j1] = fmaf(memv[j1], i1, g1 * h1);
                sq[j0] = memv[j0] * memv[j0];
                sq[j1] = memv[j1] * memv[j1];
            }
            #pragma unroll
            for (int s = 16; s; s >>= 1)
                #pragma unroll
                for (int i = 0; i < 4; i++) sq[i] += __shfl_xor_sync(~0u, sq[i], s);
            if (lane == 0) {
                red2_s[wid][0] = sq[0]; red2_s[wid][1] = sq[1];
                red2_s[wid][2] = sq[2]; red2_s[wid][3] = sq[3];
            }
            *(float4*)row = make_float4(memv[0], memv[1], memv[2], memv[3]);
            s_b[nxt][n] = s_nxt; ws_b[nxt][n] = ws_nxt;
        } else {
            const int p = q + 1;                 // pair owned: q1->2, q2->3, q3->4
            const int j0 = 2 * p, j1 = 2 * p + 1;
            float2 a = up2(hbuf[n * 6 + p]);
            float r0 = (j0 < 5) ? red_s[0][j0] + red_s[1][j0] + red_s[2][j0] + red_s[3][j0]
                                : red_s[4][j0-5] + red_s[5][j0-5] + red_s[6][j0-5] + red_s[7][j0-5];
            float r1 = (j1 < 5) ? red_s[0][j1] + red_s[1][j1] + red_s[2][j1] + red_s[3][j1]
                                : red_s[4][j1-5] + red_s[5][j1-5] + red_s[6][j1-5] + red_s[7][j1-5];
            float i0 = inv_s[j0], i1 = inv_s[j1];
            float g0 = sig(fmaf(i0, r0, sk_b[cur][j0]));
            float g1 = sig(fmaf(i1, r1, sk_b[cur][j1]));
            float h0 = fmaxf(fmaf(i0, a.x, ubn + vk_s[j0][n] + wsv), 0.f);
            float h1 = fmaxf(fmaf(i1, a.y, ubn + vk_s[j1][n] + wsv), 0.f);
            memv[0] = fmaf(memv[0], i0, g0 * h0);
            memv[1] = fmaf(memv[1], i1, g1 * h1);
            float sq0 = memv[0] * memv[0], sq1 = memv[1] * memv[1];
            #pragma unroll
            for (int s = 16; s; s >>= 1) {
                sq0 += __shfl_xor_sync(~0u, sq0, s);
                sq1 += __shfl_xor_sync(~0u, sq1, s);
            }
            if (lane == 0) { red2_s[wid][0] = sq0; red2_s[wid][1] = sq1; }
            *(float2*)(row + j0) = make_float2(memv[0], memv[1]);
            if (tid >= 128 && tid < 138) sk_b[nxt][tid - 128] = skey_nxt;
        }
        __syncthreads();   // mem(t+1) + red2_s + staging visible

        // ---- publish tagged sumsq partials ----
        if (tid < HSLOT) {
            int j = tid;
            int qo  = (j < 4) ? 0 : (j < 6) ? 1 : (j < 8) ? 2 : 3;
            int idx = (j < 4) ? j : (j - 4) & 1;
            int w0 = qo * 4;
            float v = red2_s[w0][idx] + red2_s[w0+1][idx] + red2_s[w0+2][idx] + red2_s[w0+3][idx];
            uint2 pkt; pkt.x = __float_as_uint(v); pkt.y = (unsigned)(t + 1);
            stv2(&g_part[t][half * HSLOT + j][b], pkt);
        }
    }

    // ---- final normalization ----
    if (wid < 5) {
        int j = tid >> 4, i = tid & 15;
        const uint2* pp = &g_part[NSTEP - 1][half * HSLOT + j][i];
        const unsigned want = (unsigned)NSTEP;
        uint2 v0 = ldv2(pp), v1 = ldv2(pp + 16), v2 = ldv2(pp + 32), v3 = ldv2(pp + 48);
        while ((v0.y ^ want) | (v1.y ^ want) | (v2.y ^ want) | (v3.y ^ want)) {
            v0 = ldv2(pp); v1 = ldv2(pp + 16); v2 = ldv2(pp + 32); v3 = ldv2(pp + 48);
        }
        float acc = __uint_as_float(v0.x) + __uint_as_float(v1.x)
                  + __uint_as_float(v2.x) + __uint_as_float(v3.x);
        acc += __shfl_xor_sync(~0u, acc, 8);
        acc += __shfl_xor_sync(~0u, acc, 4);
        acc += __shfl_xor_sync(~0u, acc, 2);
        acc += __shfl_xor_sync(~0u, acc, 1);
        if (i == 0) inv_s[j] = rsqrtf(acc);
    }
    __syncthreads();

    {
        float* gh = g_H + b * (NSLOT * MEMD) + half * HSLOT * MEMD;
        if (q == 0) {
            #pragma unroll
            for (int j = 0; j < 4; j++) gh[j * MEMD + n] = memv[j] * inv_s[j];
        } else {
            const int j0 = 2 * (q + 1);
            gh[j0 * MEMD + n]       = memv[0] * inv_s[j0];
            gh[(j0 + 1) * MEMD + n] = memv[1] * inv_s[j0 + 1];
        }
    }
}

// ---------- epilogue ----------
__global__ void k_epi(const int* __restrict__ q, const int* __restrict__ ans,
                      const float* __restrict__ E, const float* __restrict__ Hw,
                      const float* __restrict__ Hb, float* __restrict__ out) {
    __shared__ float red[4][NSLOT];
    __shared__ float p_s[NSLOT];
    __shared__ float u_s[MEMD];
    __shared__ float yr[4][2];
    int b = blockIdx.x, n = threadIdx.x, w = n >> 5, l = n & 31;

    float qv = 0.f;
    #pragma unroll
    for (int i = 0; i < 16; i++) qv += E[q[b * 16 + i] * MEMD + n];
    qv *= (1.f / 16.f);
    float a1 = 0.f, a2 = 0.f;
    #pragma unroll
    for (int i = 0; i < 8; i++) {
        a1 += E[ans[(b * 8 + i) * 2 + 0] * MEMD + n];
        a2 += E[ans[(b * 8 + i) * 2 + 1] * MEMD + n];
    }
    a1 *= 0.125f; a2 *= 0.125f;

    float hv[NSLOT], p[NSLOT];
    #pragma unroll
    for (int j = 0; j < NSLOT; j++) {
        hv[j] = g_H[b * (NSLOT * MEMD) + j * MEMD + n];
        p[j] = hv[j] * qv;
    }
    #pragma unroll
    for (int s = 16; s; s >>= 1)
        #pragma unroll
        for (int j = 0; j < NSLOT; j++) p[j] += __shfl_xor_sync(~0u, p[j], s);
    if (l == 0) {
        #pragma unroll
        for (int j = 0; j < NSLOT; j++) red[w][j] = p[j];
    }
    __syncthreads();
    if (n == 0) {
        float d[NSLOT], mx = -1e30f;
        #pragma unroll
        for (int j = 0; j < NSLOT; j++) {
            d[j] = red[0][j] + red[1][j] + red[2][j] + red[3][j];
            mx = fmaxf(mx, d[j]);
        }
        float sm = 0.f;
        #pragma unroll
        for (int j = 0; j < NSLOT; j++) { d[j] = expf(d[j] - mx); sm += d[j]; }
        float inv = 1.f / sm;
        #pragma unroll
        for (int j = 0; j < NSLOT; j++) p_s[j] = d[j] * inv;
    }
    __syncthreads();

    float u = 0.f;
    #pragma unroll
    for (int j = 0; j < NSLOT; j++) u = fmaf(p_s[j], hv[j], u);
    u_s[n] = u;
    __syncthreads();

    float r = qv + Hb[n];
    const float* hwr = Hw + n * MEMD;
    #pragma unroll 8
    for (int m = 0; m < MEMD; m++) r = fmaf(u_s[m], hwr[m], r);
    r = fmaxf(r, 0.f);

    float y1 = r * a1, y2 = r * a2;
    #pragma unroll
    for (int s = 16; s; s >>= 1) {
        y1 += __shfl_xor_sync(~0u, y1, s);
        y2 += __shfl_xor_sync(~0u, y2, s);
    }
    if (l == 0) { yr[w][0] = y1; yr[w][1] = y2; }
    __syncthreads();
    if (n == 0) {
        float s1 = yr[0][0] + yr[1][0] + yr[2][0] + yr[3][0];
        float s2 = yr[0][1] + yr[1][1] + yr[2][1] + yr[3][1];
        float mx = fmaxf(s1, s2);
        float e1 = expf(s1 - mx), e2 = expf(s2 - mx);
        float inv = 1.f / (e1 + e2);
        out[b * 2 + 0] = e1 * inv;
        out[b * 2 + 1] = e2 * inv;
    }
}

extern "C" void kernel_launch(void* const* d_in, const int* in_sizes, int n_in,
                              void* d_out, int out_size) {
    const int*   input_ids = (const int*)  d_in[0];
    const int*   question  = (const int*)  d_in[1];
    const int*   ans       = (const int*)  d_in[2];
    const float* E         = (const float*)d_in[3];
    const float* Uw        = (const float*)d_in[4];
    const float* Ub        = (const float*)d_in[5];
    const float* Vw        = (const float*)d_in[6];
    const float* Vb        = (const float*)d_in[7];
    const float* Ww        = (const float*)d_in[8];
    const float* Wb        = (const float*)d_in[9];
    const float* sk        = (const float*)d_in[10];
    const float* Hw        = (const float*)d_in[11];
    const float* Hb        = (const float*)d_in[12];
    float* out = (float*)d_out;

    k_setup <<<341, 128>>>(Ww, Wb, sk, Vw, Vb);
    k_gather<<<1024, 256>>>(input_ids, E);
    k_gemm  <<<128, 256>>>();
    k_main  <<<128, 512>>>(Uw, Ub);
    k_epi   <<<64, 128>>>(question, ans, E, Hw, Hb, out);
}